// round 14
// baseline (speedup 1.0000x reference)
#include <cuda_runtime.h>
#include <cuda_fp16.h>
#include <cstdint>

// TDNN as implicit GEMM, single-pass fp16 mma.sync (HMMA).
//   out[b,n,t] = relu(bias[n] + sum_{k<5,i<512} w[n][i][k] * x[b][t+k][i])
// Round 14: R13 (i-block-outer/tap-inner K order, one 136-row x tile per
// i-block serves all 5 taps, zero div/mod bookkeeping) with two bug fixes:
//   - load_B guard: ib_l + 1 < NIB  (stage 38 has k=3 at ib=7 -> OOB before)
//   - buffer toggles via explicit ternary swap (XOR toggle needed alignment
//     guarantees the smem base does not provide)

#define DIN   512
#define DOUT  512
#define TIN   1024
#define TOUT  1020
#define KW    5
#define KTOT  2560
#define BATCH 32

#define TILE_M 128
#define TILE_N 128
#define NIB    8            // i-blocks of 64 channels
#define NSTAGE 40           // 8 i-blocks x 5 taps

#define XVEC_BLOCKS ((BATCH * TIN * DIN) / 16 / 256)  // 4096
#define WPAIR_BLOCKS ((DOUT * DIN) / 256)             // 1024

// ---------------- scratch (no allocation allowed) ----------------
__device__ __half g_xh[(size_t)BATCH * TIN * DIN];
__device__ __half g_wh[DOUT * KTOT];   // [n][k*512+i]

__global__ void split_inputs(const float* __restrict__ x,
                             const float* __restrict__ w) {
    int bid = blockIdx.x;
    if (bid < XVEC_BLOCKS) {
        int i16 = (bid * 256 + threadIdx.x) * 16;
        float4 v0 = *(const float4*)(x + i16);
        float4 v1 = *(const float4*)(x + i16 + 4);
        float4 v2 = *(const float4*)(x + i16 + 8);
        float4 v3 = *(const float4*)(x + i16 + 12);
        __half2 h0 = __floats2half2_rn(v0.x, v0.y);
        __half2 h1 = __floats2half2_rn(v0.z, v0.w);
        __half2 h2 = __floats2half2_rn(v1.x, v1.y);
        __half2 h3 = __floats2half2_rn(v1.z, v1.w);
        __half2 h4 = __floats2half2_rn(v2.x, v2.y);
        __half2 h5 = __floats2half2_rn(v2.z, v2.w);
        __half2 h6 = __floats2half2_rn(v3.x, v3.y);
        __half2 h7 = __floats2half2_rn(v3.z, v3.w);
        uint4 p0, p1;
        p0.x = *(uint32_t*)&h0;  p0.y = *(uint32_t*)&h1;
        p0.z = *(uint32_t*)&h2;  p0.w = *(uint32_t*)&h3;
        p1.x = *(uint32_t*)&h4;  p1.y = *(uint32_t*)&h5;
        p1.z = *(uint32_t*)&h6;  p1.w = *(uint32_t*)&h7;
        *(uint4*)(g_xh + i16)     = p0;
        *(uint4*)(g_xh + i16 + 8) = p1;
    } else {
        int p = (bid - XVEC_BLOCKS) * 256 + threadIdx.x;   // p = n*512 + i
        int n = p >> 9;
        int i = p & 511;
        const float* wp = w + (size_t)p * KW;
        #pragma unroll
        for (int k = 0; k < KW; ++k)
            g_wh[n * KTOT + k * DIN + i] = __float2half_rn(wp[k]);
    }
}

// ---------------- PTX helpers (portable) ----------------
__device__ __forceinline__ uint32_t smem_u32(const void* p) {
    uint32_t a;
    asm("{ .reg .u64 t; cvta.to.shared.u64 t, %1; cvt.u32.u64 %0, t; }"
        : "=r"(a) : "l"(p));
    return a;
}
__device__ __forceinline__ void cpa16(uint32_t dst, const void* src) {
    asm volatile("cp.async.cg.shared.global [%0], [%1], 16;"
                 :: "r"(dst), "l"(__cvta_generic_to_global(src)) : "memory");
}
__device__ __forceinline__ void ldsm4(uint32_t* r, uint32_t a) {
    asm volatile("ldmatrix.sync.aligned.m8n8.x4.shared.b16 {%0,%1,%2,%3}, [%4];"
                 : "=r"(r[0]), "=r"(r[1]), "=r"(r[2]), "=r"(r[3]) : "r"(a));
}
__device__ __forceinline__ void mma16816(float* c, const uint32_t* a,
                                         const uint32_t* b) {
    asm volatile(
        "mma.sync.aligned.m16n8k16.row.col.f32.f16.f16.f32 "
        "{%0,%1,%2,%3}, {%4,%5,%6,%7}, {%8,%9}, {%0,%1,%2,%3};"
        : "+f"(c[0]), "+f"(c[1]), "+f"(c[2]), "+f"(c[3])
        : "r"(a[0]), "r"(a[1]), "r"(a[2]), "r"(a[3]), "r"(b[0]), "r"(b[1]));
}

// SMEM: A 3 x 16KB @ 0, B 2 x 17408B (136 rows x 128B) @ 49152
#define A_STAGE 16384u
#define B_BASE  49152u
#define B_STAGE 17408u
#define B_ROWS  136
#define SMEM_BYTES (1024 + 49152 + 2 * 17408)

extern __shared__ char dyn_smem[];

__global__ __launch_bounds__(256, 2)
void tdnn_mma(const float* __restrict__ bias, float* __restrict__ out) {
    const int tid  = threadIdx.x;
    const int wid  = tid >> 5;
    const int lane = tid & 31;
    const int d0 = blockIdx.x * TILE_M;
    const int t0 = blockIdx.y * TILE_N;
    const int b  = blockIdx.z;

    const int wm = wid & 1;   // 2 warps along M (64 rows each)
    const int wn = wid >> 1;  // 4 warps along N (32 cols each)

    const uint32_t sb = (smem_u32(dyn_smem) + 1023u) & ~1023u;
    const uint32_t B0 = sb + B_BASE;            // B buffer 0
    const uint32_t B1 = sb + B_BASE + B_STAGE;  // B buffer 1
    const uint32_t A_END = sb + 3 * A_STAGE;

    // ---- per-lane ldmatrix address precompute (SW128: 128B rows) ----
    const int grp  = lane >> 3;
    const int apar = grp >> 1;
    uint32_t a_off[4]; int a_sw[4];
    #pragma unroll
    for (int mt = 0; mt < 4; ++mt) {
        int r = wm * 64 + mt * 16 + ((grp & 1) << 3) + (lane & 7);
        a_off[mt] = (uint32_t)(r << 7);
        a_sw[mt]  = r & 7;
    }
    const int bpar  = grp & 1;
    const int ntoff = grp >> 1;
    int rbB[2];
    #pragma unroll
    for (int np = 0; np < 2; ++np)
        rbB[np] = wn * 32 + np * 16 + ntoff * 8 + (lane & 7);

    float acc[4][4][4];
    #pragma unroll
    for (int mt = 0; mt < 4; ++mt)
        #pragma unroll
        for (int nt = 0; nt < 4; ++nt)
            #pragma unroll
            for (int q = 0; q < 4; ++q) acc[mt][nt][q] = 0.0f;

    // B tile loader for i-block ib: 136 rows x 64 ch of x (all 5 tap shifts).
    auto load_B = [&](int ib, uint32_t bbase) {
        const int col0 = ib * 64;
        #pragma unroll 5
        for (int c = tid; c < B_ROWS * 8; c += 256) {
            int row = c >> 3, ch = c & 7;
            int t = min(t0 + row, TIN - 1);   // clamped rows feed only masked outputs
            uint32_t off = (uint32_t)((row << 7) | ((ch ^ (row & 7)) << 4));
            size_t gi = (size_t)b * (TIN * DIN) + (size_t)t * DIN + col0 + ch * 8;
            cpa16(bbase + off, g_xh + gi);
        }
    };
    // A tile loader: 128 rows x 64 k-cols at gmem column kc.
    auto load_A = [&](int kc, uint32_t abase) {
        #pragma unroll 4
        for (int c = tid; c < 1024; c += 256) {
            int row = c >> 3, ch = c & 7;
            uint32_t off = (uint32_t)((row << 7) | ((ch ^ (row & 7)) << 4));
            size_t gi = (size_t)(d0 + row) * KTOT + kc + ch * 8;
            cpa16(abase + off, g_wh + gi);
        }
    };

    // ---- prologue ----
    load_B(0, B0);           // group 0: B(0) + A(ib0,k0 @ kc=0)
    load_A(0, sb);
    asm volatile("cp.async.commit_group;" ::: "memory");
    load_A(512, sb + A_STAGE);   // group 1: A(ib0,k1 @ kc=512)
    asm volatile("cp.async.commit_group;" ::: "memory");

    // incremental counters (adds/selects only)
    int k_c = 0;                 // compute tap
    uint32_t abase_c = sb;       // compute A buffer
    uint32_t bbase_c = B0;       // compute B buffer
    int k_l = 2, ib_l = 0;       // load stage = s+2
    int kc_l = 2 * 512;          // gmem A column for load stage
    uint32_t abase_l = sb + 2 * A_STAGE;
    uint32_t bbase_l = B1;       // B buffer for ib_l+1

    for (int s = 0; s < NSTAGE; ++s) {
        if (s < NSTAGE - 1) asm volatile("cp.async.wait_group 1;" ::: "memory");
        else                asm volatile("cp.async.wait_group 0;" ::: "memory");
        __syncthreads();

        if (s + 2 < NSTAGE) {
            load_A(kc_l, abase_l);
            if (k_l == 3 && ib_l + 1 < NIB) load_B(ib_l + 1, bbase_l);
            asm volatile("cp.async.commit_group;" ::: "memory");
        }

        // per-stage B ldsm precompute for tap k_c
        uint32_t boffk[2]; int bswk[2];
        #pragma unroll
        for (int np = 0; np < 2; ++np) {
            int r = rbB[np] + k_c;
            boffk[np] = (uint32_t)(r << 7);
            bswk[np]  = r & 7;
        }

        #pragma unroll
        for (int kk = 0; kk < 4; ++kk) {
            uint32_t af[4][4], bf[8];
            #pragma unroll
            for (int mt = 0; mt < 4; ++mt) {
                uint32_t co = (uint32_t)((((kk << 1) + apar) ^ a_sw[mt]) << 4);
                ldsm4(af[mt], abase_c + a_off[mt] + co);
            }
            #pragma unroll
            for (int np = 0; np < 2; ++np) {
                uint32_t co = (uint32_t)((((kk << 1) + bpar) ^ bswk[np]) << 4);
                ldsm4(&bf[np * 4], bbase_c + boffk[np] + co);
            }
            #pragma unroll
            for (int mt = 0; mt < 4; ++mt)
                #pragma unroll
                for (int nt = 0; nt < 4; ++nt)
                    mma16816(acc[mt][nt], af[mt], &bf[nt * 2]);
        }

        // ---- incremental counter updates (adds & selects only) ----
        ++k_c;
        if (k_c == KW) { k_c = 0; bbase_c = (bbase_c == B0) ? B1 : B0; }
        abase_c += A_STAGE;
        if (abase_c == A_END) abase_c = sb;
        ++k_l;
        kc_l += 512;
        if (k_l == KW) {
            k_l = 0; ++ib_l; kc_l += 64 - KW * 512;
            bbase_l = (bbase_l == B0) ? B1 : B0;
        }
        abase_l += A_STAGE;
        if (abase_l == A_END) abase_l = sb;
    }

    // ---- epilogue: bias + relu; float2 stores ----
    const int quad = lane >> 2;
    const int qt   = (lane & 3) << 1;
    #pragma unroll
    for (int mt = 0; mt < 4; ++mt) {
        const int m = d0 + wm * 64 + mt * 16 + quad;
        const float bv0 = bias[m];
        const float bv1 = bias[m + 8];
        float* r0 = out + ((size_t)b * DOUT + m) * TOUT;
        float* r1 = r0 + 8 * TOUT;
        #pragma unroll
        for (int nt = 0; nt < 4; ++nt) {
            const int t = t0 + wn * 32 + nt * 8 + qt;
            if (t < TOUT) {
                float2 v0, v1;
                v0.x = fmaxf(acc[mt][nt][0] + bv0, 0.0f);
                v0.y = fmaxf(acc[mt][nt][1] + bv0, 0.0f);
                v1.x = fmaxf(acc[mt][nt][2] + bv1, 0.0f);
                v1.y = fmaxf(acc[mt][nt][3] + bv1, 0.0f);
                *(float2*)&r0[t] = v0;
                *(float2*)&r1[t] = v1;
            }
        }
    }
}

extern "C" void kernel_launch(void* const* d_in, const int* in_sizes, int n_in,
                              void* d_out, int out_size) {
    const float* x    = (const float*)d_in[0];
    const float* w    = (const float*)d_in[1];
    const float* bias = (const float*)d_in[2];
    float* out = (float*)d_out;

    cudaFuncSetAttribute(tdnn_mma, cudaFuncAttributeMaxDynamicSharedMemorySize,
                         SMEM_BYTES);

    split_inputs<<<XVEC_BLOCKS + WPAIR_BLOCKS, 256>>>(x, w);

    dim3 grid(DOUT / TILE_M, (TOUT + TILE_N - 1) / TILE_N, BATCH);  // (4,8,32)
    tdnn_mma<<<grid, 256, SMEM_BYTES>>>(bias, out);
}

// round 15
// speedup vs baseline: 1.0613x; 1.0613x over previous
#include <cuda_runtime.h>
#include <cuda_fp16.h>
#include <cstdint>

// TDNN as implicit GEMM, single-pass fp16 mma.sync (HMMA).
//   out[b,n,t] = relu(bias[n] + sum_{kappa<2560} W2[n][kappa] * x[b, t*512+kappa])
// Round 15: exactly the measured-best R12 kernel, with ONE positional change:
// load_stage(s+2) is issued AFTER kk0's ldsm+mma block instead of before it,
// so the post-barrier LDGSTS burst no longer delays the first HMMA of the
// stage (asm volatile ops issue in program order).

#define DIN   512
#define DOUT  512
#define TIN   1024
#define TOUT  1020
#define KW    5
#define KTOT  2560
#define BATCH 32

#define TILE_M 128
#define TILE_N 128
#define KC     64
#define NSTAGE (KTOT / KC)

#define XVEC_BLOCKS ((BATCH * TIN * DIN) / 16 / 256)  // 4096
#define WPAIR_BLOCKS ((DOUT * DIN) / 256)             // 1024

// ---------------- scratch (no allocation allowed) ----------------
__device__ __half g_xh[(size_t)BATCH * TIN * DIN];
__device__ __half g_wh[DOUT * KTOT];   // [n][k*512+i]

__global__ void split_inputs(const float* __restrict__ x,
                             const float* __restrict__ w) {
    int bid = blockIdx.x;
    if (bid < XVEC_BLOCKS) {
        int i16 = (bid * 256 + threadIdx.x) * 16;
        float4 v0 = *(const float4*)(x + i16);
        float4 v1 = *(const float4*)(x + i16 + 4);
        float4 v2 = *(const float4*)(x + i16 + 8);
        float4 v3 = *(const float4*)(x + i16 + 12);
        __half2 h0 = __floats2half2_rn(v0.x, v0.y);
        __half2 h1 = __floats2half2_rn(v0.z, v0.w);
        __half2 h2 = __floats2half2_rn(v1.x, v1.y);
        __half2 h3 = __floats2half2_rn(v1.z, v1.w);
        __half2 h4 = __floats2half2_rn(v2.x, v2.y);
        __half2 h5 = __floats2half2_rn(v2.z, v2.w);
        __half2 h6 = __floats2half2_rn(v3.x, v3.y);
        __half2 h7 = __floats2half2_rn(v3.z, v3.w);
        uint4 p0, p1;
        p0.x = *(uint32_t*)&h0;  p0.y = *(uint32_t*)&h1;
        p0.z = *(uint32_t*)&h2;  p0.w = *(uint32_t*)&h3;
        p1.x = *(uint32_t*)&h4;  p1.y = *(uint32_t*)&h5;
        p1.z = *(uint32_t*)&h6;  p1.w = *(uint32_t*)&h7;
        *(uint4*)(g_xh + i16)     = p0;
        *(uint4*)(g_xh + i16 + 8) = p1;
    } else {
        // one thread per (n,i): 5 contiguous fp32 reads, 5 coalesced fp16 writes
        int p = (bid - XVEC_BLOCKS) * 256 + threadIdx.x;   // p = n*512 + i
        int n = p >> 9;
        int i = p & 511;
        const float* wp = w + (size_t)p * KW;
        #pragma unroll
        for (int k = 0; k < KW; ++k)
            g_wh[n * KTOT + k * DIN + i] = __float2half_rn(wp[k]);
    }
}

// ---------------- PTX helpers (portable) ----------------
__device__ __forceinline__ uint32_t smem_u32(const void* p) {
    uint32_t a;
    asm("{ .reg .u64 t; cvta.to.shared.u64 t, %1; cvt.u32.u64 %0, t; }"
        : "=r"(a) : "l"(p));
    return a;
}
__device__ __forceinline__ void cpa16(uint32_t dst, const void* src) {
    asm volatile("cp.async.cg.shared.global [%0], [%1], 16;"
                 :: "r"(dst), "l"(__cvta_generic_to_global(src)) : "memory");
}
__device__ __forceinline__ void ldsm4(uint32_t* r, uint32_t a) {
    asm volatile("ldmatrix.sync.aligned.m8n8.x4.shared.b16 {%0,%1,%2,%3}, [%4];"
                 : "=r"(r[0]), "=r"(r[1]), "=r"(r[2]), "=r"(r[3]) : "r"(a));
}
__device__ __forceinline__ void mma16816(float* c, const uint32_t* a,
                                         const uint32_t* b) {
    asm volatile(
        "mma.sync.aligned.m16n8k16.row.col.f32.f16.f16.f32 "
        "{%0,%1,%2,%3}, {%4,%5,%6,%7}, {%8,%9}, {%0,%1,%2,%3};"
        : "+f"(c[0]), "+f"(c[1]), "+f"(c[2]), "+f"(c[3])
        : "r"(a[0]), "r"(a[1]), "r"(a[2]), "r"(a[3]), "r"(b[0]), "r"(b[1]));
}

// SMEM stage: A +0 (16KB)  B +16384 (16KB) -> 32KB/stage, 3 stages = 96KB
#define A_OFF 0u
#define B_OFF 16384u
#define STAGE_BYTES 32768u
#define NBUF 3
#define SMEM_BYTES (1024 + NBUF * 32768)

extern __shared__ char dyn_smem[];

__global__ __launch_bounds__(256, 2)
void tdnn_mma(const float* __restrict__ bias, float* __restrict__ out) {
    const int tid  = threadIdx.x;
    const int wid  = tid >> 5;
    const int lane = tid & 31;
    const int d0 = blockIdx.x * TILE_M;
    const int t0 = blockIdx.y * TILE_N;
    const int b  = blockIdx.z;

    const int wm = wid & 1;   // 2 warps along M (64 rows each)
    const int wn = wid >> 1;  // 4 warps along N (32 cols each)

    const uint32_t sb = (smem_u32(dyn_smem) + 1023u) & ~1023u;
    const int rmax = (TIN - KW) - t0;

    // ---- per-lane ldmatrix address precompute (SW128: 128B rows) ----
    const int grp  = lane >> 3;
    const int apar = grp >> 1;           // A: k-chunk parity
    uint32_t a_off[4]; int a_sw[4];
    #pragma unroll
    for (int mt = 0; mt < 4; ++mt) {
        int r = wm * 64 + mt * 16 + ((grp & 1) << 3) + (lane & 7);
        a_off[mt] = (uint32_t)(r << 7);
        a_sw[mt]  = r & 7;
    }
    const int bpar  = grp & 1;           // B: k-chunk parity
    const int ntoff = grp >> 1;
    uint32_t b_off[2]; int b_sw[2];
    #pragma unroll
    for (int np = 0; np < 2; ++np) {
        int r = wn * 32 + np * 16 + ntoff * 8 + (lane & 7);
        b_off[np] = (uint32_t)(r << 7);
        b_sw[np]  = r & 7;
    }

    float acc[4][4][4];
    #pragma unroll
    for (int mt = 0; mt < 4; ++mt)
        #pragma unroll
        for (int nt = 0; nt < 4; ++nt)
            #pragma unroll
            for (int q = 0; q < 4; ++q) acc[mt][nt][q] = 0.0f;

    auto load_stage = [&](int s, uint32_t base) {
        const int kc = s * KC;
        #pragma unroll 4
        for (int c = tid; c < 1024; c += 256) {      // A: 128 rows x 8 chunks
            int row = c >> 3, ch = c & 7;
            uint32_t off = (uint32_t)((row << 7) | ((ch ^ (row & 7)) << 4));
            size_t gi = (size_t)(d0 + row) * KTOT + kc + ch * 8;
            cpa16(base + A_OFF + off, g_wh + gi);
        }
        #pragma unroll 4
        for (int c = tid; c < 1024; c += 256) {      // B: 128 rows x 8 chunks
            int row = c >> 3, ch = c & 7;
            int t = t0 + min(row, rmax);             // clamp; outputs masked
            uint32_t off = (uint32_t)((row << 7) | ((ch ^ (row & 7)) << 4));
            size_t gi = (size_t)b * (TIN * DIN) + (size_t)t * DIN + kc + ch * 8;
            cpa16(base + B_OFF + off, g_xh + gi);
        }
        asm volatile("cp.async.commit_group;" ::: "memory");
    };

    // one kk-group of fragment loads + MMAs
    auto do_kk = [&](uint32_t base, int kk) {
        uint32_t af[4][4], bf[8];
        #pragma unroll
        for (int mt = 0; mt < 4; ++mt) {
            uint32_t co = (uint32_t)((((kk << 1) + apar) ^ a_sw[mt]) << 4);
            ldsm4(af[mt], base + A_OFF + a_off[mt] + co);
        }
        #pragma unroll
        for (int np = 0; np < 2; ++np) {
            uint32_t co = (uint32_t)((((kk << 1) + bpar) ^ b_sw[np]) << 4);
            ldsm4(&bf[np * 4], base + B_OFF + b_off[np] + co);
        }
        #pragma unroll
        for (int mt = 0; mt < 4; ++mt)
            #pragma unroll
            for (int nt = 0; nt < 4; ++nt)
                mma16816(acc[mt][nt], af[mt], &bf[nt * 2]);
    };

    load_stage(0, sb);
    load_stage(1, sb + STAGE_BYTES);

    uint32_t cbuf = 0, lbuf = 2;   // compute buf (s%3), load buf ((s+2)%3)
    for (int s = 0; s < NSTAGE; ++s) {
        if (s < NSTAGE - 1) asm volatile("cp.async.wait_group 1;" ::: "memory");
        else                asm volatile("cp.async.wait_group 0;" ::: "memory");
        __syncthreads();

        const uint32_t base = sb + cbuf * STAGE_BYTES;
        // kk0 first: queue ~64 HMMAs on the tensor pipe...
        do_kk(base, 0);
        // ...then issue the next stage's LDGSTS burst under tensor cover.
        // Buffer (s+2)%3 == (s-1)%3: drained before this barrier.
        if (s + 2 < NSTAGE) load_stage(s + 2, sb + lbuf * STAGE_BYTES);
        do_kk(base, 1);
        do_kk(base, 2);
        do_kk(base, 3);

        cbuf = (cbuf == NBUF - 1) ? 0 : cbuf + 1;
        lbuf = (lbuf == NBUF - 1) ? 0 : lbuf + 1;
    }

    // ---- epilogue: bias + relu; float2 stores ----
    const int quad = lane >> 2;
    const int qt   = (lane & 3) << 1;
    #pragma unroll
    for (int mt = 0; mt < 4; ++mt) {
        const int m = d0 + wm * 64 + mt * 16 + quad;
        const float bv0 = bias[m];
        const float bv1 = bias[m + 8];
        float* r0 = out + ((size_t)b * DOUT + m) * TOUT;
        float* r1 = r0 + 8 * TOUT;
        #pragma unroll
        for (int nt = 0; nt < 4; ++nt) {
            const int t = t0 + wn * 32 + nt * 8 + qt;
            if (t < TOUT) {
                float2 v0, v1;
                v0.x = fmaxf(acc[mt][nt][0] + bv0, 0.0f);
                v0.y = fmaxf(acc[mt][nt][1] + bv0, 0.0f);
                v1.x = fmaxf(acc[mt][nt][2] + bv1, 0.0f);
                v1.y = fmaxf(acc[mt][nt][3] + bv1, 0.0f);
                *(float2*)&r0[t] = v0;
                *(float2*)&r1[t] = v1;
            }
        }
    }
}

extern "C" void kernel_launch(void* const* d_in, const int* in_sizes, int n_in,
                              void* d_out, int out_size) {
    const float* x    = (const float*)d_in[0];
    const float* w    = (const float*)d_in[1];
    const float* bias = (const float*)d_in[2];
    float* out = (float*)d_out;

    cudaFuncSetAttribute(tdnn_mma, cudaFuncAttributeMaxDynamicSharedMemorySize,
                         SMEM_BYTES);

    split_inputs<<<XVEC_BLOCKS + WPAIR_BLOCKS, 256>>>(x, w);

    dim3 grid(DOUT / TILE_M, (TOUT + TILE_N - 1) / TILE_N, BATCH);  // (4,8,32)
    tdnn_mma<<<grid, 256, SMEM_BYTES>>>(bias, out);
}

// round 16
// speedup vs baseline: 1.0614x; 1.0002x over previous
#include <cuda_runtime.h>
#include <cuda_fp16.h>
#include <cstdint>

// TDNN as implicit GEMM, single-pass fp16 mma.sync (HMMA).
//   out[b,n,t] = relu(bias[n] + sum_{kappa<2560} W2[n][kappa] * x[b, t*512+kappa])
// Round 16: R15 (LDGSTS under tensor cover) with the burst SPLIT in half:
// A-tile cp.async after kk0, B-tile cp.async after kk1 (commit after B).
// Each half-burst is covered by its own freshly queued 64-HMMA group.

#define DIN   512
#define DOUT  512
#define TIN   1024
#define TOUT  1020
#define KW    5
#define KTOT  2560
#define BATCH 32

#define TILE_M 128
#define TILE_N 128
#define KC     64
#define NSTAGE (KTOT / KC)

#define XVEC_BLOCKS ((BATCH * TIN * DIN) / 16 / 256)  // 4096
#define WPAIR_BLOCKS ((DOUT * DIN) / 256)             // 1024

// ---------------- scratch (no allocation allowed) ----------------
__device__ __half g_xh[(size_t)BATCH * TIN * DIN];
__device__ __half g_wh[DOUT * KTOT];   // [n][k*512+i]

__global__ void split_inputs(const float* __restrict__ x,
                             const float* __restrict__ w) {
    int bid = blockIdx.x;
    if (bid < XVEC_BLOCKS) {
        int i16 = (bid * 256 + threadIdx.x) * 16;
        float4 v0 = *(const float4*)(x + i16);
        float4 v1 = *(const float4*)(x + i16 + 4);
        float4 v2 = *(const float4*)(x + i16 + 8);
        float4 v3 = *(const float4*)(x + i16 + 12);
        __half2 h0 = __floats2half2_rn(v0.x, v0.y);
        __half2 h1 = __floats2half2_rn(v0.z, v0.w);
        __half2 h2 = __floats2half2_rn(v1.x, v1.y);
        __half2 h3 = __floats2half2_rn(v1.z, v1.w);
        __half2 h4 = __floats2half2_rn(v2.x, v2.y);
        __half2 h5 = __floats2half2_rn(v2.z, v2.w);
        __half2 h6 = __floats2half2_rn(v3.x, v3.y);
        __half2 h7 = __floats2half2_rn(v3.z, v3.w);
        uint4 p0, p1;
        p0.x = *(uint32_t*)&h0;  p0.y = *(uint32_t*)&h1;
        p0.z = *(uint32_t*)&h2;  p0.w = *(uint32_t*)&h3;
        p1.x = *(uint32_t*)&h4;  p1.y = *(uint32_t*)&h5;
        p1.z = *(uint32_t*)&h6;  p1.w = *(uint32_t*)&h7;
        *(uint4*)(g_xh + i16)     = p0;
        *(uint4*)(g_xh + i16 + 8) = p1;
    } else {
        // one thread per (n,i): 5 contiguous fp32 reads, 5 coalesced fp16 writes
        int p = (bid - XVEC_BLOCKS) * 256 + threadIdx.x;   // p = n*512 + i
        int n = p >> 9;
        int i = p & 511;
        const float* wp = w + (size_t)p * KW;
        #pragma unroll
        for (int k = 0; k < KW; ++k)
            g_wh[n * KTOT + k * DIN + i] = __float2half_rn(wp[k]);
    }
}

// ---------------- PTX helpers (portable) ----------------
__device__ __forceinline__ uint32_t smem_u32(const void* p) {
    uint32_t a;
    asm("{ .reg .u64 t; cvta.to.shared.u64 t, %1; cvt.u32.u64 %0, t; }"
        : "=r"(a) : "l"(p));
    return a;
}
__device__ __forceinline__ void cpa16(uint32_t dst, const void* src) {
    asm volatile("cp.async.cg.shared.global [%0], [%1], 16;"
                 :: "r"(dst), "l"(__cvta_generic_to_global(src)) : "memory");
}
__device__ __forceinline__ void ldsm4(uint32_t* r, uint32_t a) {
    asm volatile("ldmatrix.sync.aligned.m8n8.x4.shared.b16 {%0,%1,%2,%3}, [%4];"
                 : "=r"(r[0]), "=r"(r[1]), "=r"(r[2]), "=r"(r[3]) : "r"(a));
}
__device__ __forceinline__ void mma16816(float* c, const uint32_t* a,
                                         const uint32_t* b) {
    asm volatile(
        "mma.sync.aligned.m16n8k16.row.col.f32.f16.f16.f32 "
        "{%0,%1,%2,%3}, {%4,%5,%6,%7}, {%8,%9}, {%0,%1,%2,%3};"
        : "+f"(c[0]), "+f"(c[1]), "+f"(c[2]), "+f"(c[3])
        : "r"(a[0]), "r"(a[1]), "r"(a[2]), "r"(a[3]), "r"(b[0]), "r"(b[1]));
}

// SMEM stage: A +0 (16KB)  B +16384 (16KB) -> 32KB/stage, 3 stages = 96KB
#define A_OFF 0u
#define B_OFF 16384u
#define STAGE_BYTES 32768u
#define NBUF 3
#define SMEM_BYTES (1024 + NBUF * 32768)

extern __shared__ char dyn_smem[];

__global__ __launch_bounds__(256, 2)
void tdnn_mma(const float* __restrict__ bias, float* __restrict__ out) {
    const int tid  = threadIdx.x;
    const int wid  = tid >> 5;
    const int lane = tid & 31;
    const int d0 = blockIdx.x * TILE_M;
    const int t0 = blockIdx.y * TILE_N;
    const int b  = blockIdx.z;

    const int wm = wid & 1;   // 2 warps along M (64 rows each)
    const int wn = wid >> 1;  // 4 warps along N (32 cols each)

    const uint32_t sb = (smem_u32(dyn_smem) + 1023u) & ~1023u;
    const int rmax = (TIN - KW) - t0;

    // ---- per-lane ldmatrix address precompute (SW128: 128B rows) ----
    const int grp  = lane >> 3;
    const int apar = grp >> 1;           // A: k-chunk parity
    uint32_t a_off[4]; int a_sw[4];
    #pragma unroll
    for (int mt = 0; mt < 4; ++mt) {
        int r = wm * 64 + mt * 16 + ((grp & 1) << 3) + (lane & 7);
        a_off[mt] = (uint32_t)(r << 7);
        a_sw[mt]  = r & 7;
    }
    const int bpar  = grp & 1;           // B: k-chunk parity
    const int ntoff = grp >> 1;
    uint32_t b_off[2]; int b_sw[2];
    #pragma unroll
    for (int np = 0; np < 2; ++np) {
        int r = wn * 32 + np * 16 + ntoff * 8 + (lane & 7);
        b_off[np] = (uint32_t)(r << 7);
        b_sw[np]  = r & 7;
    }

    float acc[4][4][4];
    #pragma unroll
    for (int mt = 0; mt < 4; ++mt)
        #pragma unroll
        for (int nt = 0; nt < 4; ++nt)
            #pragma unroll
            for (int q = 0; q < 4; ++q) acc[mt][nt][q] = 0.0f;

    // A half: 4 cp.async per thread
    auto load_A = [&](int s, uint32_t base) {
        const int kc = s * KC;
        #pragma unroll 4
        for (int c = tid; c < 1024; c += 256) {
            int row = c >> 3, ch = c & 7;
            uint32_t off = (uint32_t)((row << 7) | ((ch ^ (row & 7)) << 4));
            size_t gi = (size_t)(d0 + row) * KTOT + kc + ch * 8;
            cpa16(base + A_OFF + off, g_wh + gi);
        }
    };
    // B half: 4 cp.async per thread, commits the group
    auto load_B = [&](int s, uint32_t base) {
        const int kc = s * KC;
        #pragma unroll 4
        for (int c = tid; c < 1024; c += 256) {
            int row = c >> 3, ch = c & 7;
            int t = t0 + min(row, rmax);             // clamp; outputs masked
            uint32_t off = (uint32_t)((row << 7) | ((ch ^ (row & 7)) << 4));
            size_t gi = (size_t)b * (TIN * DIN) + (size_t)t * DIN + kc + ch * 8;
            cpa16(base + B_OFF + off, g_xh + gi);
        }
        asm volatile("cp.async.commit_group;" ::: "memory");
    };

    // one kk-group of fragment loads + MMAs
    auto do_kk = [&](uint32_t base, int kk) {
        uint32_t af[4][4], bf[8];
        #pragma unroll
        for (int mt = 0; mt < 4; ++mt) {
            uint32_t co = (uint32_t)((((kk << 1) + apar) ^ a_sw[mt]) << 4);
            ldsm4(af[mt], base + A_OFF + a_off[mt] + co);
        }
        #pragma unroll
        for (int np = 0; np < 2; ++np) {
            uint32_t co = (uint32_t)((((kk << 1) + bpar) ^ b_sw[np]) << 4);
            ldsm4(&bf[np * 4], base + B_OFF + b_off[np] + co);
        }
        #pragma unroll
        for (int mt = 0; mt < 4; ++mt)
            #pragma unroll
            for (int nt = 0; nt < 4; ++nt)
                mma16816(acc[mt][nt], af[mt], &bf[nt * 2]);
    };

    load_A(0, sb);                 load_B(0, sb);
    load_A(1, sb + STAGE_BYTES);   load_B(1, sb + STAGE_BYTES);

    uint32_t cbuf = 0, lbuf = 2;   // compute buf (s%3), load buf ((s+2)%3)
    for (int s = 0; s < NSTAGE; ++s) {
        if (s < NSTAGE - 1) asm volatile("cp.async.wait_group 1;" ::: "memory");
        else                asm volatile("cp.async.wait_group 0;" ::: "memory");
        __syncthreads();

        const uint32_t base  = sb + cbuf * STAGE_BYTES;
        const uint32_t lbase = sb + lbuf * STAGE_BYTES;
        const bool more = (s + 2 < NSTAGE);
        // kk0 queues ~64 HMMAs, then the A half-burst issues under cover;
        // kk1 requeues, then the B half-burst (+commit) issues under cover.
        // Target buffer (s+2)%3 == (s-1)%3: drained before this barrier.
        do_kk(base, 0);
        if (more) load_A(s + 2, lbase);
        do_kk(base, 1);
        if (more) load_B(s + 2, lbase);
        do_kk(base, 2);
        do_kk(base, 3);

        cbuf = (cbuf == NBUF - 1) ? 0 : cbuf + 1;
        lbuf = (lbuf == NBUF - 1) ? 0 : lbuf + 1;
    }

    // ---- epilogue: bias + relu; float2 stores ----
    const int quad = lane >> 2;
    const int qt   = (lane & 3) << 1;
    #pragma unroll
    for (int mt = 0; mt < 4; ++mt) {
        const int m = d0 + wm * 64 + mt * 16 + quad;
        const float bv0 = bias[m];
        const float bv1 = bias[m + 8];
        float* r0 = out + ((size_t)b * DOUT + m) * TOUT;
        float* r1 = r0 + 8 * TOUT;
        #pragma unroll
        for (int nt = 0; nt < 4; ++nt) {
            const int t = t0 + wn * 32 + nt * 8 + qt;
            if (t < TOUT) {
                float2 v0, v1;
                v0.x = fmaxf(acc[mt][nt][0] + bv0, 0.0f);
                v0.y = fmaxf(acc[mt][nt][1] + bv0, 0.0f);
                v1.x = fmaxf(acc[mt][nt][2] + bv1, 0.0f);
                v1.y = fmaxf(acc[mt][nt][3] + bv1, 0.0f);
                *(float2*)&r0[t] = v0;
                *(float2*)&r1[t] = v1;
            }
        }
    }
}

extern "C" void kernel_launch(void* const* d_in, const int* in_sizes, int n_in,
                              void* d_out, int out_size) {
    const float* x    = (const float*)d_in[0];
    const float* w    = (const float*)d_in[1];
    const float* bias = (const float*)d_in[2];
    float* out = (float*)d_out;

    cudaFuncSetAttribute(tdnn_mma, cudaFuncAttributeMaxDynamicSharedMemorySize,
                         SMEM_BYTES);

    split_inputs<<<XVEC_BLOCKS + WPAIR_BLOCKS, 256>>>(x, w);

    dim3 grid(DOUT / TILE_M, (TOUT + TILE_N - 1) / TILE_N, BATCH);  // (4,8,32)
    tdnn_mma<<<grid, 256, SMEM_BYTES>>>(bias, out);
}